// round 8
// baseline (speedup 1.0000x reference)
#include <cuda_runtime.h>
#include <cstdint>
#include <cstddef>

#define TB   128   // batch
#define TT   512   // time steps
#define EE   256   // embedding dim
#define HH   256   // hidden dim
#define G4   1024  // 4*H gate width
#define VV   32000 // vocab
#define NCLS 32    // classes
#define NCTA 128   // persistent grid size (<=148 SMs -> co-resident guaranteed)

#define HSTRIDE 260                       // padded k-stride for sh_h (16B-aligned)
#define STOK_INTS   (16 * TT)             // 8,192 ints = 32,768 B
#define DYN_BYTES   (STOK_INTS * 4)

// ---- static device scratch (no allocations allowed) ----
__device__ float g_embW[(size_t)2 * VV * G4];   // [dir][V][4H]  = 262 MB
__device__ float g_hbuf[2 * 2 * TB * HH];       // [buf][dir][b][j] double-buffered h
__device__ int   g_fd[NCTA];                    // dense barrier flags (coalesced poll)

__device__ __forceinline__ float sigm(float x) { return 1.0f / (1.0f + __expf(-x)); }

// packed fp32x2 FMA (FFMA2) — bit-exact 2x fp32, sm_100+ PTX
#define FMA_F32X2(d, a, b, c) \
    asm("fma.rn.f32x2 %0, %1, %2, %3;" : "=l"(d) : "l"(a), "l"(b), "l"(c))
#define UNPACK_F32X2(lo, hi, in) \
    asm("mov.b64 {%0, %1}, %2;" : "=f"(lo), "=f"(hi) : "l"(in))
#define PACK_DUP_F32X2(out, x) \
    asm("mov.b64 %0, {%1, %1};" : "=l"(out) : "r"(x))
#define PACK_F32X2(out, lo, hi) \
    asm("mov.b64 %0, {%1, %2};" : "=l"(out) : "f"(lo), "f"(hi))

// ============================================================================
// Kernel 1: embW[d][v][g] = sum_e emb[v][e] * W_d[e][g]
// grid (V/32, 2, 2), block 256. Tile: 32 v x 512 g-cols (2 cols/thread).
// (unchanged from R7: 732 us measured)
// ============================================================================
__global__ void __launch_bounds__(256, 2) k_embW(const float* __restrict__ emb,
                                                 const float* __restrict__ Wf,
                                                 const float* __restrict__ Wb)
{
    __shared__ float she[256][36];   // [e][v], v-contiguous, 16B-aligned rows
    const int v0  = blockIdx.x * 32;
    const int gt  = blockIdx.y;
    const int d   = blockIdx.z;
    const int tid = threadIdx.x;
    const float* __restrict__ W = d ? Wb : Wf;

    for (int idx = tid; idx < 32 * 256; idx += 256) {
        int vl = idx >> 8, e = idx & 255;
        she[e][vl] = emb[(size_t)(v0 + vl) * EE + e];   // coalesced over e
    }
    __syncthreads();

    const int g = gt * 256 + tid;                       // col A; col B = g+512
    unsigned long long accA[16], accB[16];              // lanes = (v=2q, v=2q+1)
#pragma unroll
    for (int q = 0; q < 16; ++q) { accA[q] = 0ull; accB[q] = 0ull; }

    const float* __restrict__ WgA = W + g;
    const float* __restrict__ WgB = W + g + 512;
#pragma unroll 2
    for (int e = 0; e < 256; ++e) {
        float wA = WgA[(size_t)e * G4];
        float wB = WgB[(size_t)e * G4];
        unsigned long long wA2, wB2;
        PACK_DUP_F32X2(wA2, __float_as_int(wA));
        PACK_DUP_F32X2(wB2, __float_as_int(wB));
#pragma unroll
        for (int p = 0; p < 8; ++p) {
            ulonglong2 a = *(const ulonglong2*)&she[e][p * 4]; // broadcast LDS.128
            FMA_F32X2(accA[2 * p],     a.x, wA2, accA[2 * p]);
            FMA_F32X2(accA[2 * p + 1], a.y, wA2, accA[2 * p + 1]);
            FMA_F32X2(accB[2 * p],     a.x, wB2, accB[2 * p]);
            FMA_F32X2(accB[2 * p + 1], a.y, wB2, accB[2 * p + 1]);
        }
    }
    size_t base = ((size_t)d * VV + v0) * G4 + g;
#pragma unroll
    for (int q = 0; q < 16; ++q) {
        float lo, hi;
        UNPACK_F32X2(lo, hi, accA[q]);
        g_embW[base + (size_t)(2 * q) * G4]           = lo;
        g_embW[base + (size_t)(2 * q + 1) * G4]       = hi;
        UNPACK_F32X2(lo, hi, accB[q]);
        g_embW[base + (size_t)(2 * q) * G4 + 512]     = lo;
        g_embW[base + (size_t)(2 * q + 1) * G4 + 512] = hi;
    }
}

// ============================================================================
// Kernel 2: persistent bidirectional LSTM recurrence.
// 128 CTAs x 512 threads. CTA = (dir, 16 b, 32 strided gate cols = 128 z-cols).
// Thread = (col cl 0..127, k-quarter kq 0..3): owns U[col][k0..k0+63] in
// REGISTERS (32 packed u64). Batch rows processed in TWO PASSES of 8 with
// acc2[8] live -> ~110 regs total, no spill (R7 spilled with acc2[16]).
// Inner loop: only h broadcast LDS.128 -> fma/crossbar co-bound.
// ============================================================================
__global__ void __launch_bounds__(512, 1) k_lstm(const void* __restrict__ tokens_raw,
                                                 const float* __restrict__ Uf,
                                                 const float* __restrict__ bf,
                                                 const float* __restrict__ Ub,
                                                 const float* __restrict__ bb)
{
    extern __shared__ char dyn[];
    int* __restrict__ stok = (int*)dyn;               // [16][TT]

    __shared__ float sh_h[16][HSTRIDE];   // [b][k] h tile, k-contiguous
    __shared__ float sz[4][16][128];      // k-quarter partials [kq][b][cl]

    const int id  = blockIdx.x;
    const int jt  = id & 7;
    const int bt  = (id >> 3) & 7;
    const int d   = id >> 6;
    const int tid = threadIdx.x;

    const float* __restrict__ U   = d ? Ub : Uf;
    const float* __restrict__ bia = d ? bb : bf;

    const int b0      = bt * 16;
    const int colbase = jt * 32;
    // ---- GEMM-phase mapping: cl = column, kq = k-quarter ----
    const int kq  = tid >> 7;               // 0..3
    const int cl  = tid & 127;              // gate-local column 0..127
    const int col = colbase + (cl & 31) + ((cl >> 5) << 8);
    const int k0  = kq * 64;
    // ---- gate-phase mapping (one cell per thread) ----
    const int gbl = tid >> 5;               // 0..15 local batch row
    const int gjj = tid & 31;               // 0..31 local hidden col

    // ---- runtime token dtype probe: int64 high words are all zero ----
    const int*       __restrict__ t32 = (const int*)tokens_raw;
    const long long* __restrict__ t64 = (const long long*)tokens_raw;
    int probe = 0;
#pragma unroll
    for (int i = 1; i < 64; i += 2) probe |= t32[i];
    const bool tok32 = (probe != 0);

    // ---- one-time: U column slice into registers (packed k-pairs) ----
    unsigned long long u2[32];
#pragma unroll
    for (int i = 0; i < 32; ++i) {
        float ulo = U[(size_t)(k0 + 2 * i)     * G4 + col];  // coalesced over cl
        float uhi = U[(size_t)(k0 + 2 * i + 1) * G4 + col];
        PACK_F32X2(u2[i], ulo, uhi);
    }
    // tokens for this CTA's 16 batch rows
    for (int idx = tid; idx < STOK_INTS; idx += 512) {
        int bl = idx >> 9, t = idx & (TT - 1);
        stok[idx] = tok32 ? t32[(b0 + bl) * TT + t]
                          : (int)t64[(b0 + bl) * TT + t];
    }
    const int base = *(volatile int*)&g_fd[id];   // uniform at launch
    __syncthreads();

    // per-gate-thread constants / state
    float bq[4];
#pragma unroll
    for (int q = 0; q < 4; ++q) bq[q] = bia[colbase + gjj + q * 256];
    float creg = 0.f;

    // prefetch xw for step 0
    float xnext[4];
    {
        const int ts0 = d ? (TT - 1) : 0;
        int tk = stok[gbl * TT + ts0];
        size_t gb = ((size_t)d * VV + tk) * G4 + colbase + gjj;
#pragma unroll
        for (int q = 0; q < 4; ++q) xnext[q] = g_embW[gb + q * 256];
    }

    for (int s = 0; s < TT; ++s) {
        const bool haveh = (s > 0);
        if (haveh) {   // stage h from buffer written at step s-1
            const int rb = s & 1;
            const float* __restrict__ hsrc =
                g_hbuf + ((size_t)(rb * 2 + d) * TB + b0) * HH;
#pragma unroll
            for (int i = 0; i < 2; ++i) {            // 1024 float4 slots
                int idx = tid + i * 512;
                int bl = idx >> 6, kc = idx & 63;
                *(float4*)&sh_h[bl][kc * 4] =
                    *(const float4*)&hsrc[bl * HH + kc * 4];
            }
            __syncthreads();
        }

        // ---- GEMM: two passes of 8 rows, acc2[8] live (no spill) ----
#pragma unroll
        for (int half = 0; half < 2; ++half) {
            unsigned long long acc2[8];
#pragma unroll
            for (int r = 0; r < 8; ++r) acc2[r] = 0ull;
            if (haveh) {
                const int r0 = half * 8;
#pragma unroll 4
                for (int c = 0; c < 16; ++c) {       // 4 k per chunk
                    const int kk = k0 + c * 4;
                    unsigned long long ua = u2[2 * c], ub = u2[2 * c + 1];
#pragma unroll
                    for (int r = 0; r < 8; ++r) {
                        ulonglong2 hv =
                            *(const ulonglong2*)&sh_h[r0 + r][kk]; // broadcast
                        FMA_F32X2(acc2[r], hv.x, ua, acc2[r]);
                        FMA_F32X2(acc2[r], hv.y, ub, acc2[r]);
                    }
                }
            }
#pragma unroll
            for (int r = 0; r < 8; ++r) {
                float lo, hi;
                UNPACK_F32X2(lo, hi, acc2[r]);
                sz[kq][half * 8 + r][cl] = lo + hi;  // lanes cl -> conflict-free
            }
        }
        __syncthreads();

        // ---- gate update: one cell per thread; c stays in a register ----
        {
            float zi = xnext[0] + bq[0];
            float zf = xnext[1] + bq[1];
            float zg = xnext[2] + bq[2];
            float zo = xnext[3] + bq[3];
#pragma unroll
            for (int q4 = 0; q4 < 4; ++q4) {
                zi += sz[q4][gbl][gjj];
                zf += sz[q4][gbl][32 + gjj];
                zg += sz[q4][gbl][64 + gjj];
                zo += sz[q4][gbl][96 + gjj];
            }
            float cn = sigm(zf) * creg + sigm(zi) * tanhf(zg);
            float h  = sigm(zo) * tanhf(cn);
            creg = cn;
            g_hbuf[((size_t)(((s + 1) & 1) * 2 + d) * TB + (b0 + gbl)) * HH
                   + colbase + gjj] = h;
        }
        // prefetch xw for step s+1 (off the critical path, before barrier)
        if (s + 1 < TT) {
            const int ts1 = d ? (TT - 2 - s) : (s + 1);
            int tk = stok[gbl * TT + ts1];
            size_t gb = ((size_t)d * VV + tk) * G4 + colbase + gjj;
#pragma unroll
            for (int q = 0; q < 4; ++q) xnext[q] = g_embW[gb + q * 256];
        }
        __syncthreads();

        // ---- grid barrier: dense flags, coalesced poll (no atomics) ----
        if (tid == 0) {
            __threadfence();                         // release all CTA stores
            *(volatile int*)&g_fd[id] = base + s + 1;
        }
        if (tid < NCTA) {
            const volatile int* f = &g_fd[tid];      // warp-coalesced poll
            const int target = base + s + 1;
            while (*f - target < 0) { }
            __threadfence();        // acquire + L1D invalidate
        }
        __syncthreads();
    }
}

// ============================================================================
// Kernel 3: head. One block per batch row.
// h_cat[512] -> relu(dense 256) -> logits 32 -> softmax. Final h in buf 0.
// ============================================================================
__global__ void __launch_bounds__(256) k_head(const float* __restrict__ W1,
                                              const float* __restrict__ b1,
                                              const float* __restrict__ W2,
                                              const float* __restrict__ b2,
                                              float* __restrict__ out)
{
    __shared__ float sh[512];
    __shared__ float sy[256];
    __shared__ float red[8][33];
    const int b = blockIdx.x, tid = threadIdx.x;

    sh[tid]       = g_hbuf[((size_t)0 * TB + b) * HH + tid]; // fwd (buf0, dir0)
    sh[256 + tid] = g_hbuf[((size_t)1 * TB + b) * HH + tid]; // bwd (buf0, dir1)
    __syncthreads();

    float a = b1[tid];
    for (int k = 0; k < 512; ++k) a = fmaf(sh[k], W1[(size_t)k * HH + tid], a);
    sy[tid] = fmaxf(a, 0.f);
    __syncthreads();

    const int part = tid >> 5, c = tid & 31;
    float p = 0.f;
#pragma unroll
    for (int kk = 0; kk < 32; ++kk) {
        int k = part * 32 + kk;
        p = fmaf(sy[k], W2[(size_t)k * NCLS + c], p);
    }
    red[part][c] = p;
    __syncthreads();

    if (tid < 32) {
        float l = b2[tid];
#pragma unroll
        for (int q = 0; q < 8; ++q) l += red[q][tid];
        float m = l;
#pragma unroll
        for (int off = 16; off; off >>= 1)
            m = fmaxf(m, __shfl_xor_sync(0xffffffffu, m, off));
        float e = __expf(l - m);
        float ssum = e;
#pragma unroll
        for (int off = 16; off; off >>= 1)
            ssum += __shfl_xor_sync(0xffffffffu, ssum, off);
        out[b * NCLS + tid] = e / ssum;
    }
}

// ============================================================================
extern "C" void kernel_launch(void* const* d_in, const int* in_sizes, int n_in,
                              void* d_out, int out_size)
{
    const void*  tokens = d_in[0];
    const float* emb = (const float*)d_in[1];
    const float* Wf  = (const float*)d_in[2];
    const float* Uf  = (const float*)d_in[3];
    const float* bf  = (const float*)d_in[4];
    const float* Wb  = (const float*)d_in[5];
    const float* Ub  = (const float*)d_in[6];
    const float* bb  = (const float*)d_in[7];
    const float* W1  = (const float*)d_in[8];
    const float* b1  = (const float*)d_in[9];
    const float* W2  = (const float*)d_in[10];
    const float* b2  = (const float*)d_in[11];
    float* out = (float*)d_out;

    cudaFuncSetAttribute(k_lstm, cudaFuncAttributeMaxDynamicSharedMemorySize,
                         DYN_BYTES);

    k_embW<<<dim3(VV / 32, 2, 2), 256>>>(emb, Wf, Wb);
    k_lstm<<<NCTA, 512, DYN_BYTES>>>(tokens, Uf, bf, Ub, bb);
    k_head<<<TB, 256>>>(W1, b1, W2, b2, out);
}

// round 13
// speedup vs baseline: 1.2628x; 1.2628x over previous
#include <cuda_runtime.h>
#include <cstdint>
#include <cstddef>

#define TB   128   // batch
#define TT   512   // time steps
#define EE   256   // embedding dim
#define HH   256   // hidden dim
#define G4   1024  // 4*H gate width
#define VV   32000 // vocab
#define NCLS 32    // classes
#define NCTA 128   // persistent grid size (<=148 SMs -> co-resident guaranteed)

#define HSTRIDE 260                       // padded k-stride for sh_h (16B-aligned)
// dynamic smem: swizzled U only (128 rows x 64 granules x 16B)
#define SU4_BYTES   (128 * 64 * 16)       // 131,072 B
#define DYN_BYTES   SU4_BYTES

// ---- static device scratch (no allocations allowed) ----
__device__ float g_embW[(size_t)2 * VV * G4];   // [dir][V][4H]  = 262 MB
__device__ float g_hbuf[2 * 2 * TB * HH];       // [buf][dir][b][j] double-buffered h
__device__ int   g_fd[NCTA];                    // dense barrier flags (coalesced poll)

__device__ __forceinline__ float sigm(float x) { return 1.0f / (1.0f + __expf(-x)); }

// packed fp32x2 FMA (FFMA2) — bit-exact 2x fp32, sm_100+ PTX
#define FMA_F32X2(d, a, b, c) \
    asm("fma.rn.f32x2 %0, %1, %2, %3;" : "=l"(d) : "l"(a), "l"(b), "l"(c))
#define UNPACK_F32X2(lo, hi, in) \
    asm("mov.b64 {%0, %1}, %2;" : "=f"(lo), "=f"(hi) : "l"(in))
#define PACK_DUP_F32X2(out, x) \
    asm("mov.b64 %0, {%1, %1};" : "=l"(out) : "r"(x))

// ============================================================================
// Kernel 1: embW[d][v][g] = sum_e emb[v][e] * W_d[e][g]
// (unchanged: 727 us measured in R8)
// ============================================================================
__global__ void __launch_bounds__(256, 2) k_embW(const float* __restrict__ emb,
                                                 const float* __restrict__ Wf,
                                                 const float* __restrict__ Wb)
{
    __shared__ float she[256][36];   // [e][v], v-contiguous, 16B-aligned rows
    const int v0  = blockIdx.x * 32;
    const int gt  = blockIdx.y;
    const int d   = blockIdx.z;
    const int tid = threadIdx.x;
    const float* __restrict__ W = d ? Wb : Wf;

    for (int idx = tid; idx < 32 * 256; idx += 256) {
        int vl = idx >> 8, e = idx & 255;
        she[e][vl] = emb[(size_t)(v0 + vl) * EE + e];   // coalesced over e
    }
    __syncthreads();

    const int g = gt * 256 + tid;                       // col A; col B = g+512
    unsigned long long accA[16], accB[16];              // lanes = (v=2q, v=2q+1)
#pragma unroll
    for (int q = 0; q < 16; ++q) { accA[q] = 0ull; accB[q] = 0ull; }

    const float* __restrict__ WgA = W + g;
    const float* __restrict__ WgB = W + g + 512;
#pragma unroll 2
    for (int e = 0; e < 256; ++e) {
        float wA = WgA[(size_t)e * G4];
        float wB = WgB[(size_t)e * G4];
        unsigned long long wA2, wB2;
        PACK_DUP_F32X2(wA2, __float_as_int(wA));
        PACK_DUP_F32X2(wB2, __float_as_int(wB));
#pragma unroll
        for (int p = 0; p < 8; ++p) {
            ulonglong2 a = *(const ulonglong2*)&she[e][p * 4]; // broadcast LDS.128
            FMA_F32X2(accA[2 * p],     a.x, wA2, accA[2 * p]);
            FMA_F32X2(accA[2 * p + 1], a.y, wA2, accA[2 * p + 1]);
            FMA_F32X2(accB[2 * p],     a.x, wB2, accB[2 * p]);
            FMA_F32X2(accB[2 * p + 1], a.y, wB2, accB[2 * p + 1]);
        }
    }
    size_t base = ((size_t)d * VV + v0) * G4 + g;
#pragma unroll
    for (int q = 0; q < 16; ++q) {
        float lo, hi;
        UNPACK_F32X2(lo, hi, accA[q]);
        g_embW[base + (size_t)(2 * q) * G4]           = lo;
        g_embW[base + (size_t)(2 * q + 1) * G4]       = hi;
        UNPACK_F32X2(lo, hi, accB[q]);
        g_embW[base + (size_t)(2 * q) * G4 + 512]     = lo;
        g_embW[base + (size_t)(2 * q + 1) * G4 + 512] = hi;
    }
}

// ============================================================================
// Kernel 2: persistent bidirectional LSTM recurrence.
// 128 CTAs x 512 threads. CTA = (dir, 16 b, 128 local gate cols).
// Thread (kq 0..3, bh 0..1, cl 0..63): 2 cols (cl, cl+64) x 8 b x 64 k.
// U in XOR-swizzled smem (16B granule g' = g ^ (row&7)) -> 4-wf loads.
// Each h broadcast LDS.128 feeds 4 FFMA2 -> crossbar/fma co-bound.
// Tokens read directly from global (prefetched, off critical path).
// Total smem: 131,072 dyn + 49,408 static = 180.5 KB/SM.
// ============================================================================
__global__ void __launch_bounds__(512, 1) k_lstm(const void* __restrict__ tokens_raw,
                                                 const float* __restrict__ Uf,
                                                 const float* __restrict__ bf,
                                                 const float* __restrict__ Ub,
                                                 const float* __restrict__ bb)
{
    extern __shared__ char dyn[];
    float* __restrict__ sU4 = (float*)dyn;          // [128 rows][64 granules][4]

    __shared__ float sh_h[16][HSTRIDE];   // [b][k] h tile, k-contiguous
    __shared__ float sz[4][16][128];      // k-quarter partials [kq][b][localcol]

    const int id  = blockIdx.x;
    const int jt  = id & 7;
    const int bt  = (id >> 3) & 7;
    const int d   = id >> 6;
    const int tid = threadIdx.x;

    const float* __restrict__ U   = d ? Ub : Uf;
    const float* __restrict__ bia = d ? bb : bf;

    const int b0      = bt * 16;
    const int colbase = jt * 32;
    // ---- GEMM-phase mapping ----
    const int kq  = tid >> 7;               // k-quarter 0..3
    const int bh  = (tid >> 6) & 1;         // batch half 0/1
    const int cl  = tid & 63;               // col A local; col B = cl+64
    const int k0  = kq * 64;
    const int swzA = cl & 7;                // row swizzle (rowB = cl+64: same &7)
    // ---- gate-phase mapping (one cell per thread) ----
    const int gbl = tid >> 5;               // 0..15 local batch row
    const int gjj = tid & 31;               // 0..31 local hidden col

    // ---- runtime token dtype probe: int64 high words are all zero ----
    const int*       __restrict__ t32 = (const int*)tokens_raw;
    const long long* __restrict__ t64 = (const long long*)tokens_raw;
    int probe = 0;
#pragma unroll
    for (int i = 1; i < 64; i += 2) probe |= t32[i];
    const bool tok32 = (probe != 0);
    const int  brow  = b0 + gbl;            // this thread's global batch row

    // ---- one-time: stage U into swizzled smem ----
    // local row lr (0..127) -> global col: colbase + (lr&31) + ((lr>>5)<<8)
    // granule G = k>>2 (0..63), physical index G ^ (lr & 7); float slot k&3.
    for (int idx = tid; idx < 128 * 256; idx += 512) {
        const int lr = idx & 127;           // lanes: consecutive lr -> coalesced
        const int k  = idx >> 7;
        const int gc = colbase + (lr & 31) + ((lr >> 5) << 8);
        const int gp = (k >> 2) ^ (lr & 7);
        sU4[(lr * 64 + gp) * 4 + (k & 3)] = U[(size_t)k * G4 + gc];
    }
    const int base = *(volatile int*)&g_fd[id];   // uniform at launch
    __syncthreads();

    // per-gate-thread constants / state
    float bq[4];
#pragma unroll
    for (int q = 0; q < 4; ++q) bq[q] = bia[colbase + gjj + q * 256];
    float creg = 0.f;

    // prefetch xw for step 0 (token read: warp-broadcast LDG)
    float xnext[4];
    {
        const int ts0 = d ? (TT - 1) : 0;
        int tk = tok32 ? t32[brow * TT + ts0] : (int)t64[brow * TT + ts0];
        size_t gb = ((size_t)d * VV + tk) * G4 + colbase + gjj;
#pragma unroll
        for (int q = 0; q < 4; ++q) xnext[q] = g_embW[gb + q * 256];
    }

    const float* __restrict__ UrowA = sU4 + (cl        * 64 + kq * 16) * 4;
    const float* __restrict__ UrowB = sU4 + ((cl + 64) * 64 + kq * 16) * 4;

    for (int s = 0; s < TT; ++s) {
        const bool haveh = (s > 0);
        if (haveh) {   // stage h written at step s-1 (buffer s&1)
            const int rb = s & 1;
            const float* __restrict__ hsrc =
                g_hbuf + ((size_t)(rb * 2 + d) * TB + b0) * HH;
#pragma unroll
            for (int i = 0; i < 2; ++i) {            // 1024 float4 slots
                int idx = tid + i * 512;
                int bl = idx >> 6, kc = idx & 63;
                *(float4*)&sh_h[bl][kc * 4] =
                    *(const float4*)&hsrc[bl * HH + kc * 4];
            }
            __syncthreads();
        }

        unsigned long long accA[8], accB[8];   // [b] k-paired partials
#pragma unroll
        for (int r = 0; r < 8; ++r) { accA[r] = 0ull; accB[r] = 0ull; }

        if (haveh) {
#pragma unroll 2
            for (int g = 0; g < 16; ++g) {           // 16 granules of 4 k
                const int gp = g ^ swzA;             // swizzled granule index
                ulonglong2 uA = *(const ulonglong2*)&UrowA[gp * 4]; // 4-wf LDS
                ulonglong2 uB = *(const ulonglong2*)&UrowB[gp * 4];
                const int kk = k0 + g * 4;
#pragma unroll
                for (int r = 0; r < 8; ++r) {
                    ulonglong2 hv =
                        *(const ulonglong2*)&sh_h[bh * 8 + r][kk]; // broadcast
                    FMA_F32X2(accA[r], hv.x, uA.x, accA[r]);
                    FMA_F32X2(accA[r], hv.y, uA.y, accA[r]);
                    FMA_F32X2(accB[r], hv.x, uB.x, accB[r]);
                    FMA_F32X2(accB[r], hv.y, uB.y, accB[r]);
                }
            }
        }
        // write k-quarter partials (lanes cl -> conflict-free STS)
#pragma unroll
        for (int r = 0; r < 8; ++r) {
            float lo, hi;
            UNPACK_F32X2(lo, hi, accA[r]);
            sz[kq][bh * 8 + r][cl]      = lo + hi;
            UNPACK_F32X2(lo, hi, accB[r]);
            sz[kq][bh * 8 + r][cl + 64] = lo + hi;
        }
        __syncthreads();

        // ---- gate update: one cell per thread; c stays in a register ----
        {
            float zi = xnext[0] + bq[0];
            float zf = xnext[1] + bq[1];
            float zg = xnext[2] + bq[2];
            float zo = xnext[3] + bq[3];
#pragma unroll
            for (int q4 = 0; q4 < 4; ++q4) {
                zi += sz[q4][gbl][gjj];
                zf += sz[q4][gbl][32 + gjj];
                zg += sz[q4][gbl][64 + gjj];
                zo += sz[q4][gbl][96 + gjj];
            }
            float cn = sigm(zf) * creg + sigm(zi) * tanhf(zg);
            float h  = sigm(zo) * tanhf(cn);
            creg = cn;
            g_hbuf[((size_t)(((s + 1) & 1) * 2 + d) * TB + (b0 + gbl)) * HH
                   + colbase + gjj] = h;
        }
        // prefetch xw for step s+1 (off the critical path, before barrier)
        if (s + 1 < TT) {
            const int ts1 = d ? (TT - 2 - s) : (s + 1);
            int tk = tok32 ? t32[brow * TT + ts1] : (int)t64[brow * TT + ts1];
            size_t gb = ((size_t)d * VV + tk) * G4 + colbase + gjj;
#pragma unroll
            for (int q = 0; q < 4; ++q) xnext[q] = g_embW[gb + q * 256];
        }
        __syncthreads();

        // ---- grid barrier: dense flags, coalesced poll (no atomics) ----
        if (tid == 0) {
            __threadfence();                         // release all CTA stores
            *(volatile int*)&g_fd[id] = base + s + 1;
        }
        if (tid < NCTA) {
            const volatile int* f = &g_fd[tid];      // warp-coalesced poll
            const int target = base + s + 1;
            while (*f - target < 0) { }
            __threadfence();        // acquire + L1D invalidate
        }
        __syncthreads();
    }
}

// ============================================================================
// Kernel 3: head. One block per batch row.
// ============================================================================
__global__ void __launch_bounds__(256) k_head(const float* __restrict__ W1,
                                              const float* __restrict__ b1,
                                              const float* __restrict__ W2,
                                              const float* __restrict__ b2,
                                              float* __restrict__ out)
{
    __shared__ float sh[512];
    __shared__ float sy[256];
    __shared__ float red[8][33];
    const int b = blockIdx.x, tid = threadIdx.x;

    sh[tid]       = g_hbuf[((size_t)0 * TB + b) * HH + tid]; // fwd (buf0, dir0)
    sh[256 + tid] = g_hbuf[((size_t)1 * TB + b) * HH + tid]; // bwd (buf0, dir1)
    __syncthreads();

    float a = b1[tid];
    for (int k = 0; k < 512; ++k) a = fmaf(sh[k], W1[(size_t)k * HH + tid], a);
    sy[tid] = fmaxf(a, 0.f);
    __syncthreads();

    const int part = tid >> 5, c = tid & 31;
    float p = 0.f;
#pragma unroll
    for (int kk = 0; kk < 32; ++kk) {
        int k = part * 32 + kk;
        p = fmaf(sy[k], W2[(size_t)k * NCLS + c], p);
    }
    red[part][c] = p;
    __syncthreads();

    if (tid < 32) {
        float l = b2[tid];
#pragma unroll
        for (int q = 0; q < 8; ++q) l += red[q][tid];
        float m = l;
#pragma unroll
        for (int off = 16; off; off >>= 1)
            m = fmaxf(m, __shfl_xor_sync(0xffffffffu, m, off));
        float e = __expf(l - m);
        float ssum = e;
#pragma unroll
        for (int off = 16; off; off >>= 1)
            ssum += __shfl_xor_sync(0xffffffffu, ssum, off);
        out[b * NCLS + tid] = e / ssum;
    }
}

// ============================================================================
extern "C" void kernel_launch(void* const* d_in, const int* in_sizes, int n_in,
                              void* d_out, int out_size)
{
    const void*  tokens = d_in[0];
    const float* emb = (const float*)d_in[1];
    const float* Wf  = (const float*)d_in[2];
    const float* Uf  = (const float*)d_in[3];
    const float* bf  = (const float*)d_in[4];
    const float* Wb  = (const float*)d_in[5];
    const float* Ub  = (const float*)d_in[6];
    const float* bb  = (const float*)d_in[7];
    const float* W1  = (const float*)d_in[8];
    const float* b1  = (const float*)d_in[9];
    const float* W2  = (const float*)d_in[10];
    const float* b2  = (const float*)d_in[11];
    float* out = (float*)d_out;

    cudaFuncSetAttribute(k_lstm, cudaFuncAttributeMaxDynamicSharedMemorySize,
                         DYN_BYTES);

    k_embW<<<dim3(VV / 32, 2, 2), 256>>>(emb, Wf, Wb);
    k_lstm<<<NCTA, 512, DYN_BYTES>>>(tokens, Uf, bf, Ub, bb);
    k_head<<<TB, 256>>>(W1, b1, W2, b2, out);
}